// round 14
// baseline (speedup 1.0000x reference)
#include <cuda_runtime.h>
#include <cuda_bf16.h>
#include <cstdint>

#define NB 8
#define NC 256
#define NHW 4096
#define ND 32

typedef unsigned long long ull;

// Static device scratch
__device__ __nv_bfloat16 g_Qb[NB][NHW][ND];    // q * log2(e), [b][n][d] bf16
__device__ __nv_bfloat16 g_Kb[NB][NHW][ND];    // [b][n][d] bf16
__device__ __nv_bfloat16 g_Vb[NB][NC][NHW];    // [b][e][n] bf16

// ---------------------------------------------------------------------------
// helpers
// ---------------------------------------------------------------------------
__device__ __forceinline__ uint32_t smem_u32(const void* p) {
    uint32_t a;
    asm("{ .reg .u64 t; cvta.to.shared.u64 t, %1; cvt.u32.u64 %0, t; }"
        : "=r"(a) : "l"(p));
    return a;
}
__device__ __forceinline__ float fexp2(float v) {
    float r; asm("ex2.approx.ftz.f32 %0, %1;" : "=f"(r) : "f"(v)); return r;
}
// d = {hi, lo} packed bf16x2
__device__ __forceinline__ uint32_t pack_bf16(float hi, float lo) {
    uint32_t r; asm("cvt.rn.bf16x2.f32 %0, %1, %2;" : "=r"(r) : "f"(hi), "f"(lo));
    return r;
}
__device__ __forceinline__ void mma_bf16(float c[4], const uint32_t a[4],
                                         uint32_t b0, uint32_t b1) {
    asm volatile(
        "mma.sync.aligned.m16n8k16.row.col.f32.bf16.bf16.f32 "
        "{%0,%1,%2,%3}, {%4,%5,%6,%7}, {%8,%9}, {%0,%1,%2,%3};"
        : "+f"(c[0]), "+f"(c[1]), "+f"(c[2]), "+f"(c[3])
        : "r"(a[0]), "r"(a[1]), "r"(a[2]), "r"(a[3]), "r"(b0), "r"(b1));
}
__device__ __forceinline__ void ldmx4(uint32_t r[4], uint32_t a) {
    asm volatile("ldmatrix.sync.aligned.m8n8.x4.shared.b16 {%0,%1,%2,%3}, [%4];"
        : "=r"(r[0]), "=r"(r[1]), "=r"(r[2]), "=r"(r[3]) : "r"(a));
}
__device__ __forceinline__ void ldmx4t(uint32_t r[4], uint32_t a) {
    asm volatile("ldmatrix.sync.aligned.m8n8.x4.trans.shared.b16 {%0,%1,%2,%3}, [%4];"
        : "=r"(r[0]), "=r"(r[1]), "=r"(r[2]), "=r"(r[3]) : "r"(a));
}
__device__ __forceinline__ void cpa16(uint32_t s, const void* g) {
    asm volatile("cp.async.cg.shared.global [%0], [%1], 16;"
                 :: "r"(s), "l"(__cvta_generic_to_global(g)) : "memory");
}
#define CP_COMMIT() asm volatile("cp.async.commit_group;" ::: "memory")
#define CP_WAIT2()  asm volatile("cp.async.wait_group 2;" ::: "memory")
#define CP_WAIT1()  asm volatile("cp.async.wait_group 1;" ::: "memory")
#define CP_WAIT0()  asm volatile("cp.async.wait_group 0;" ::: "memory")

// ============================================================================
// Kernel A: fused QKV projection, bf16 tensor cores (unchanged, ~15us).
// ============================================================================
#define QW_PITCH 528
#define OFF_W 0
#define OFF_BIAS 33792
#define OFF_X 34048
#define QKV_SMEM2 50944

__global__ __launch_bounds__(256) void qkv_kernel(
    const float* __restrict__ x,
    const float* __restrict__ Wq, const float* __restrict__ bq,
    const float* __restrict__ Wk, const float* __restrict__ bk,
    const float* __restrict__ Wv, const float* __restrict__ bv)
{
    extern __shared__ char sm[];
    const uint32_t sb = smem_u32(sm);
    const int b = blockIdx.z;
    const int oc0 = blockIdx.y * 64;
    const int n0 = blockIdx.x * 256;
    const int t = threadIdx.x, wid = t >> 5, lane = t & 31;
    const int wOC = wid & 1, wN = wid >> 1;
    const int r = lane >> 2, tq = lane & 3;

    #pragma unroll
    for (int l = 0; l < 16; l++) {
        int idx = t + l * 256;
        int row = idx >> 6, c4 = idx & 63;
        const float* src;
        if (oc0 == 0) src = (row < 32) ? &Wq[row * 256 + c4 * 4]
                                       : &Wk[(row - 32) * 256 + c4 * 4];
        else          src = &Wv[(oc0 - 64 + row) * 256 + c4 * 4];
        float4 w = *(const float4*)src;
        *(uint2*)(sm + OFF_W + row * QW_PITCH + c4 * 8) =
            make_uint2(pack_bf16(w.y, w.x), pack_bf16(w.w, w.z));
    }
    if (t < 64) {
        float bias;
        if (oc0 == 0) bias = (t < 32) ? bq[t] : bk[t - 32];
        else          bias = bv[oc0 - 64 + t];
        ((float*)(sm + OFF_BIAS))[t] = bias;
    }

    float acc[2][8][4];
    #pragma unroll
    for (int m = 0; m < 2; m++)
        #pragma unroll
        for (int j = 0; j < 8; j++)
            #pragma unroll
            for (int q = 0; q < 4; q++) acc[m][j][q] = 0.f;

    float4 xr[8];
    #pragma unroll
    for (int l = 0; l < 8; l++) {
        int idx = t + l * 256;
        int cc = idx >> 6, n4 = idx & 63;
        xr[l] = *(const float4*)&x[(b * NC + cc) * NHW + n0 + n4 * 4];
    }

    for (int ch = 0; ch < 8; ch++) {
        __syncthreads();
        #pragma unroll
        for (int l = 0; l < 8; l++) {
            int idx = t + l * 256;
            int cc = idx >> 6, n4 = idx & 63;
            *(uint2*)(sm + OFF_X + cc * QW_PITCH + n4 * 8) =
                make_uint2(pack_bf16(xr[l].y, xr[l].x), pack_bf16(xr[l].w, xr[l].z));
        }
        __syncthreads();
        if (ch + 1 < 8) {
            int c0n = (ch + 1) * 32;
            #pragma unroll
            for (int l = 0; l < 8; l++) {
                int idx = t + l * 256;
                int cc = idx >> 6, n4 = idx & 63;
                xr[l] = *(const float4*)&x[(b * NC + c0n + cc) * NHW + n0 + n4 * 4];
            }
        }
        #pragma unroll
        for (int ks = 0; ks < 2; ks++) {
            const int cb = ks * 16;
            uint32_t a0[4], a1[4];
            uint32_t wadr = sb + OFF_W + (wOC * 32 + (lane & 15)) * QW_PITCH
                            + (ch * 32 + cb) * 2 + (lane >> 4) * 16;
            ldmx4(a0, wadr);
            ldmx4(a1, wadr + 16 * QW_PITCH);
            uint32_t bt[4][4];
            #pragma unroll
            for (int nb = 0; nb < 4; nb++) {
                uint32_t xadr = sb + OFF_X
                    + (cb + (lane & 7) + ((lane >> 3) & 1) * 8) * QW_PITCH
                    + (wN * 64 + nb * 16 + (lane >> 4) * 8) * 2;
                ldmx4t(bt[nb], xadr);
            }
            #pragma unroll
            for (int nb = 0; nb < 4; nb++) {
                mma_bf16(acc[0][nb * 2],     a0, bt[nb][0], bt[nb][1]);
                mma_bf16(acc[0][nb * 2 + 1], a0, bt[nb][2], bt[nb][3]);
                mma_bf16(acc[1][nb * 2],     a1, bt[nb][0], bt[nb][1]);
                mma_bf16(acc[1][nb * 2 + 1], a1, bt[nb][2], bt[nb][3]);
            }
        }
    }
    __syncthreads();

    const float* bs = (const float*)(sm + OFF_BIAS);
    float bm[2][2];
    bm[0][0] = bs[wOC * 32 + r];      bm[0][1] = bs[wOC * 32 + r + 8];
    bm[1][0] = bs[wOC * 32 + 16 + r]; bm[1][1] = bs[wOC * 32 + 16 + r + 8];
    __syncthreads();

    if (oc0 == 0) {
        const float scl = (wOC == 0) ? 1.4426950408889634f : 1.0f;
        #pragma unroll
        for (int m = 0; m < 2; m++) {
            int oc_r0 = wOC * 32 + m * 16 + r;
            #pragma unroll
            for (int j = 0; j < 8; j++) {
                int n_ = wN * 64 + j * 8 + tq * 2;
                *(__nv_bfloat16*)(sm + n_ * 144 + oc_r0 * 2) =
                    __float2bfloat16((acc[m][j][0] + bm[m][0]) * scl);
                *(__nv_bfloat16*)(sm + (n_ + 1) * 144 + oc_r0 * 2) =
                    __float2bfloat16((acc[m][j][1] + bm[m][0]) * scl);
                *(__nv_bfloat16*)(sm + n_ * 144 + (oc_r0 + 8) * 2) =
                    __float2bfloat16((acc[m][j][2] + bm[m][1]) * scl);
                *(__nv_bfloat16*)(sm + (n_ + 1) * 144 + (oc_r0 + 8) * 2) =
                    __float2bfloat16((acc[m][j][3] + bm[m][1]) * scl);
            }
        }
        __syncthreads();
        #pragma unroll
        for (int l = 0; l < 4; l++) {
            int idx = t + l * 256;
            int nn = idx >> 2, c4 = idx & 3;
            *(float4*)&g_Qb[b][n0 + nn][c4 * 8] =
                *(const float4*)(sm + nn * 144 + c4 * 16);
            *(float4*)&g_Kb[b][n0 + nn][c4 * 8] =
                *(const float4*)(sm + nn * 144 + 64 + c4 * 16);
        }
    } else {
        #pragma unroll
        for (int m = 0; m < 2; m++) {
            int row0 = wOC * 32 + m * 16 + r;
            #pragma unroll
            for (int j = 0; j < 8; j++) {
                int n_ = wN * 64 + j * 8 + tq * 2;
                *(uint32_t*)(sm + row0 * 528 + n_ * 2) =
                    pack_bf16(acc[m][j][1] + bm[m][0], acc[m][j][0] + bm[m][0]);
                *(uint32_t*)(sm + (row0 + 8) * 528 + n_ * 2) =
                    pack_bf16(acc[m][j][3] + bm[m][1], acc[m][j][2] + bm[m][1]);
            }
        }
        __syncthreads();
        #pragma unroll
        for (int l = 0; l < 8; l++) {
            int idx = t + l * 256;
            int row = idx >> 5, n16 = idx & 31;
            *(float4*)&g_Vb[b][oc0 - 64 + row][n0 + n16 * 8] =
                *(const float4*)(sm + row * 528 + n16 * 16);
        }
    }
}

// ============================================================================
// Kernel B: flash attention, FULL-E CTA (64q x 256E), 512 threads.
// 16 warps = 2 wM (32 q-rows) x 8 wE (32 E-cols). Per iter:
//   - each warp QK+exp+pack its 32 rows x 8-key eighth of tile i+1
//     (1 K-ldmx4, 4 MMAs, 8 exp/lane), publishes half-k16 A-frags (uint2);
//   - PV(i): assembles all 8 k16 A-frag slots for its rows from pbuf,
//     32 MMAs over its 32 E-cols.
// QK + exp computed ONCE chip-wide (no E-half duplication). Pipeline = R12/13.
// ============================================================================
#define OFF_Q 0                 // 64 x 80B
#define OFF_K 5120              // 3 x 5120
#define OFF_V 20480             // 3 x 36864 (256e x 144B)
#define OFF_PB 131072           // 2 x 8192: [m16(4)][k16(4)][half(2)] x 256B
#define OFF_SUM 147456          // 8 x 64 f32
#define ATTN_SMEM_B 149504

__global__ __launch_bounds__(512, 1) void attn_kernel(
    const float* __restrict__ x,
    const float* __restrict__ gamma_p,
    float* __restrict__ out)
{
    extern __shared__ char smem[];
    const uint32_t sb = smem_u32(smem);
    const int t = threadIdx.x, wid = t >> 5, lane = t & 31;
    const int b = blockIdx.y;
    const int n0 = blockIdx.x * 64;
    const int wM = wid & 1, wE = wid >> 1;   // 2 x 8
    const int r = lane >> 2, tq = lane & 3;

    // ---- prologue: G0={Q,K0}  G1={V0,K1}  G2={V1} ----
    if (t < 256) {
        int row = t >> 2, ch = t & 3;
        cpa16(sb + OFF_Q + row * 80 + ch * 16, &g_Qb[b][n0 + row][ch * 8]);
        cpa16(sb + OFF_K + row * 80 + ch * 16, &g_Kb[b][row][ch * 8]);
    }
    CP_COMMIT();
    #pragma unroll
    for (int l = 0; l < 4; l++) {
        int idx = t + l * 512;
        int e = idx >> 3, ch = idx & 7;
        cpa16(sb + OFF_V + e * 144 + ch * 16, &g_Vb[b][e][ch * 8]);
    }
    if (t < 256) {
        int row = t >> 2, ch = t & 3;
        cpa16(sb + OFF_K + 5120 + row * 80 + ch * 16, &g_Kb[b][64 + row][ch * 8]);
    }
    CP_COMMIT();
    #pragma unroll
    for (int l = 0; l < 4; l++) {
        int idx = t + l * 512;
        int e = idx >> 3, ch = idx & 7;
        cpa16(sb + OFF_V + 36864 + e * 144 + ch * 16, &g_Vb[b][e][64 + ch * 8]);
    }
    CP_COMMIT();

    CP_WAIT2();                  // G0 done: Q + K0 resident
    __syncthreads();

    // persistent Q fragments: qa[m16 half][d-kstep]
    uint32_t qa[2][2][4];
    #pragma unroll
    for (int m = 0; m < 2; m++) {
        uint32_t qaddr = sb + OFF_Q + (wM * 32 + m * 16 + (lane & 15)) * 80
                         + (lane >> 4) * 16;
        ldmx4(qa[m][0], qaddr);
        ldmx4(qa[m][1], qaddr + 32);
    }
    const uint32_t k_off = (lane & 7) * 80 + (lane >> 3) * 16;
    const uint32_t v_off = (wE * 32 + (lane & 7)) * 144 + (lane >> 3) * 16;
    const int k16_own = wE >> 1, half_own = wE & 1;

    float o[2][4][4];            // [m16 half][eb 8-col group][frag]
    #pragma unroll
    for (int m = 0; m < 2; m++)
        #pragma unroll
        for (int eb = 0; eb < 4; eb++)
            #pragma unroll
            for (int j = 0; j < 4; j++) o[m][eb][j] = 0.f;
    float sums_r[2][2] = {{0.f, 0.f}, {0.f, 0.f}};

    // ---- compute P(J) for own 32 rows x 8-key eighth, publish halves ----
    #define COMPUTE_P_HALF(J)                                                     \
    {                                                                             \
        const uint32_t kb_ = sb + OFF_K + ((J) % 3) * 5120;                       \
        const int pb_off = OFF_PB + ((J) & 1) * 8192;                             \
        uint32_t kf[4];                                                           \
        ldmx4(kf, kb_ + (wE * 8) * 80 + k_off);                                   \
        _Pragma("unroll")                                                         \
        for (int m = 0; m < 2; m++) {                                             \
            float c_[4];                                                          \
            c_[0] = c_[1] = c_[2] = c_[3] = 0.f;                                  \
            mma_bf16(c_, qa[m][0], kf[0], kf[1]);                                 \
            mma_bf16(c_, qa[m][1], kf[2], kf[3]);                                 \
            float p0 = fexp2(c_[0]), p1 = fexp2(c_[1]);                           \
            float p2 = fexp2(c_[2]), p3 = fexp2(c_[3]);                           \
            sums_r[m][0] += p0 + p1;                                              \
            sums_r[m][1] += p2 + p3;                                              \
            *(uint2*)((char*)smem + pb_off                                        \
                + ((((wM * 2 + m) * 4 + k16_own) * 2 + half_own) * 32 + lane) * 8)\
                = make_uint2(pack_bf16(p1, p0), pack_bf16(p3, p2));               \
        }                                                                         \
    }

    COMPUTE_P_HALF(0);

    for (int i = 0; i < 64; i++) {
        if (i < 63) { CP_WAIT1(); } else { CP_WAIT0(); }
        __syncthreads();               // V(i)+K(i+1) ready; P(i) exchange visible

        if (i + 2 < 64) {              // prefetch tile i+2: K group, then V group
            int m0 = (i + 2) * 64;
            if (t < 256) {
                int row = t >> 2, ch = t & 3;
                cpa16(sb + OFF_K + ((i + 2) % 3) * 5120 + row * 80 + ch * 16,
                      &g_Kb[b][m0 + row][ch * 8]);
            }
            CP_COMMIT();
            uint32_t vst = sb + OFF_V + ((i + 2) % 3) * 36864;
            #pragma unroll
            for (int l = 0; l < 4; l++) {
                int idx = t + l * 512;
                int e = idx >> 3, ch = idx & 7;
                cpa16(vst + e * 144 + ch * 16, &g_Vb[b][e][m0 + ch * 8]);
            }
            CP_COMMIT();
        }

        if (i + 1 < 64) COMPUTE_P_HALF(i + 1);

        // ---- PV(i): A-frags from pbuf[i&1], V frags from ring slot i%3 ----
        const uint32_t vb = sb + OFF_V + (i % 3) * 36864;
        const int pb = OFF_PB + (i & 1) * 8192;
        #pragma unroll
        for (int kp = 0; kp < 2; kp++) {           // 32-key halves
            uint32_t pau[2][2][4];                 // [m][k16 within half]
            #pragma unroll
            for (int m = 0; m < 2; m++)
                #pragma unroll
                for (int s2 = 0; s2 < 2; s2++) {
                    int base = pb + ((((wM * 2 + m) * 4 + kp * 2 + s2) * 2) * 32
                                     + lane) * 8;
                    uint2 lo = *(const uint2*)((char*)smem + base);
                    uint2 hi = *(const uint2*)((char*)smem + base + 256);
                    pau[m][s2][0] = lo.x; pau[m][s2][1] = lo.y;
                    pau[m][s2][2] = hi.x; pau[m][s2][3] = hi.y;
                }
            #pragma unroll
            for (int eb = 0; eb < 4; eb++) {
                uint32_t v[4];
                ldmx4(v, vb + v_off + eb * 1152 + kp * 64);
                #pragma unroll
                for (int m = 0; m < 2; m++) {
                    mma_bf16(o[m][eb], pau[m][0], v[0], v[1]);
                    mma_bf16(o[m][eb], pau[m][1], v[2], v[3]);
                }
            }
        }
    }

    // ---- merge rowsum eighths across the 8 wE warps ----
    #pragma unroll
    for (int m = 0; m < 2; m++)
        #pragma unroll
        for (int h = 0; h < 2; h++) {
            sums_r[m][h] += __shfl_xor_sync(0xffffffffu, sums_r[m][h], 1);
            sums_r[m][h] += __shfl_xor_sync(0xffffffffu, sums_r[m][h], 2);
        }
    float* sums = (float*)(smem + OFF_SUM);   // [8 wE][64 rows]
    __syncthreads();
    if (tq == 0) {
        #pragma unroll
        for (int m = 0; m < 2; m++)
            #pragma unroll
            for (int h = 0; h < 2; h++)
                sums[wE * 64 + wM * 32 + m * 16 + h * 8 + r] = sums_r[m][h];
    }
    __syncthreads();
    const float g = gamma_p[0];
    float scl[2][2];
    #pragma unroll
    for (int m = 0; m < 2; m++)
        #pragma unroll
        for (int h = 0; h < 2; h++) {
            int row = wM * 32 + m * 16 + h * 8 + r;
            float s = 0.f;
            #pragma unroll
            for (int w = 0; w < 8; w++) s += sums[w * 64 + row];
            scl[m][h] = g / s;
        }

    __syncthreads();
    float* os = (float*)smem;                 // [64][265] f32
    #pragma unroll
    for (int m = 0; m < 2; m++)
        #pragma unroll
        for (int eb = 0; eb < 4; eb++) {
            int e = wE * 32 + eb * 8 + 2 * tq;
            int row0 = wM * 32 + m * 16 + r;
            os[row0 * 265 + e]           = o[m][eb][0] * scl[m][0];
            os[row0 * 265 + e + 1]       = o[m][eb][1] * scl[m][0];
            os[(row0 + 8) * 265 + e]     = o[m][eb][2] * scl[m][1];
            os[(row0 + 8) * 265 + e + 1] = o[m][eb][3] * scl[m][1];
        }
    __syncthreads();
    #pragma unroll 8
    for (int l = 0; l < 32; l++) {
        int idx = t + l * 512;
        int n = idx & 63, e = idx >> 6;
        int gi = (b * NC + e) * NHW + n0 + n;
        out[gi] = os[n * 265 + e] + x[gi];
    }
}

// ============================================================================
extern "C" void kernel_launch(void* const* d_in, const int* in_sizes, int n_in,
                              void* d_out, int out_size) {
    (void)in_sizes; (void)n_in; (void)out_size;
    const float* x     = (const float*)d_in[0];
    const float* Wq    = (const float*)d_in[1];
    const float* bq    = (const float*)d_in[2];
    const float* Wk    = (const float*)d_in[3];
    const float* bk    = (const float*)d_in[4];
    const float* Wv    = (const float*)d_in[5];
    const float* bv    = (const float*)d_in[6];
    const float* gamma = (const float*)d_in[7];
    float* out = (float*)d_out;

    cudaFuncSetAttribute(qkv_kernel,
                         cudaFuncAttributeMaxDynamicSharedMemorySize, QKV_SMEM2);
    cudaFuncSetAttribute(attn_kernel,
                         cudaFuncAttributeMaxDynamicSharedMemorySize, ATTN_SMEM_B);

    dim3 gA(16, 5, NB);
    qkv_kernel<<<gA, 256, QKV_SMEM2>>>(x, Wq, bq, Wk, bk, Wv, bv);

    dim3 gB(64, NB);
    attn_kernel<<<gB, 512, ATTN_SMEM_B>>>(x, gamma, out);
}

// round 15
// speedup vs baseline: 1.0259x; 1.0259x over previous
#include <cuda_runtime.h>
#include <cuda_bf16.h>
#include <cstdint>

#define NB 8
#define NC 256
#define NHW 4096
#define ND 32

typedef unsigned long long ull;

// Static device scratch
__device__ __nv_bfloat16 g_Qb[NB][NHW][ND];    // q * log2(e), [b][n][d] bf16
__device__ __nv_bfloat16 g_Kb[NB][NHW][ND];    // [b][n][d] bf16
__device__ __nv_bfloat16 g_Vb[NB][NC][NHW];    // [b][e][n] bf16

// ---------------------------------------------------------------------------
// helpers
// ---------------------------------------------------------------------------
__device__ __forceinline__ uint32_t smem_u32(const void* p) {
    uint32_t a;
    asm("{ .reg .u64 t; cvta.to.shared.u64 t, %1; cvt.u32.u64 %0, t; }"
        : "=r"(a) : "l"(p));
    return a;
}
__device__ __forceinline__ float fexp2(float v) {
    float r; asm("ex2.approx.ftz.f32 %0, %1;" : "=f"(r) : "f"(v)); return r;
}
// d = {hi, lo} packed bf16x2
__device__ __forceinline__ uint32_t pack_bf16(float hi, float lo) {
    uint32_t r; asm("cvt.rn.bf16x2.f32 %0, %1, %2;" : "=r"(r) : "f"(hi), "f"(lo));
    return r;
}
__device__ __forceinline__ void mma_bf16(float c[4], const uint32_t a[4],
                                         uint32_t b0, uint32_t b1) {
    asm volatile(
        "mma.sync.aligned.m16n8k16.row.col.f32.bf16.bf16.f32 "
        "{%0,%1,%2,%3}, {%4,%5,%6,%7}, {%8,%9}, {%0,%1,%2,%3};"
        : "+f"(c[0]), "+f"(c[1]), "+f"(c[2]), "+f"(c[3])
        : "r"(a[0]), "r"(a[1]), "r"(a[2]), "r"(a[3]), "r"(b0), "r"(b1));
}
__device__ __forceinline__ void ldmx4(uint32_t r[4], uint32_t a) {
    asm volatile("ldmatrix.sync.aligned.m8n8.x4.shared.b16 {%0,%1,%2,%3}, [%4];"
        : "=r"(r[0]), "=r"(r[1]), "=r"(r[2]), "=r"(r[3]) : "r"(a));
}
__device__ __forceinline__ void ldmx4t(uint32_t r[4], uint32_t a) {
    asm volatile("ldmatrix.sync.aligned.m8n8.x4.trans.shared.b16 {%0,%1,%2,%3}, [%4];"
        : "=r"(r[0]), "=r"(r[1]), "=r"(r[2]), "=r"(r[3]) : "r"(a));
}
__device__ __forceinline__ void cpa16(uint32_t s, const void* g) {
    asm volatile("cp.async.cg.shared.global [%0], [%1], 16;"
                 :: "r"(s), "l"(__cvta_generic_to_global(g)) : "memory");
}
#define CP_COMMIT() asm volatile("cp.async.commit_group;" ::: "memory")
#define CP_WAIT2()  asm volatile("cp.async.wait_group 2;" ::: "memory")
#define CP_WAIT1()  asm volatile("cp.async.wait_group 1;" ::: "memory")
#define CP_WAIT0()  asm volatile("cp.async.wait_group 0;" ::: "memory")

// ============================================================================
// Kernel A: fused QKV projection, bf16 tensor cores (unchanged, ~15us).
// ============================================================================
#define QW_PITCH 528
#define OFF_W 0
#define OFF_BIAS 33792
#define OFF_X 34048
#define QKV_SMEM2 50944

__global__ __launch_bounds__(256) void qkv_kernel(
    const float* __restrict__ x,
    const float* __restrict__ Wq, const float* __restrict__ bq,
    const float* __restrict__ Wk, const float* __restrict__ bk,
    const float* __restrict__ Wv, const float* __restrict__ bv)
{
    extern __shared__ char sm[];
    const uint32_t sb = smem_u32(sm);
    const int b = blockIdx.z;
    const int oc0 = blockIdx.y * 64;
    const int n0 = blockIdx.x * 256;
    const int t = threadIdx.x, wid = t >> 5, lane = t & 31;
    const int wOC = wid & 1, wN = wid >> 1;
    const int r = lane >> 2, tq = lane & 3;

    #pragma unroll
    for (int l = 0; l < 16; l++) {
        int idx = t + l * 256;
        int row = idx >> 6, c4 = idx & 63;
        const float* src;
        if (oc0 == 0) src = (row < 32) ? &Wq[row * 256 + c4 * 4]
                                       : &Wk[(row - 32) * 256 + c4 * 4];
        else          src = &Wv[(oc0 - 64 + row) * 256 + c4 * 4];
        float4 w = *(const float4*)src;
        *(uint2*)(sm + OFF_W + row * QW_PITCH + c4 * 8) =
            make_uint2(pack_bf16(w.y, w.x), pack_bf16(w.w, w.z));
    }
    if (t < 64) {
        float bias;
        if (oc0 == 0) bias = (t < 32) ? bq[t] : bk[t - 32];
        else          bias = bv[oc0 - 64 + t];
        ((float*)(sm + OFF_BIAS))[t] = bias;
    }

    float acc[2][8][4];
    #pragma unroll
    for (int m = 0; m < 2; m++)
        #pragma unroll
        for (int j = 0; j < 8; j++)
            #pragma unroll
            for (int q = 0; q < 4; q++) acc[m][j][q] = 0.f;

    float4 xr[8];
    #pragma unroll
    for (int l = 0; l < 8; l++) {
        int idx = t + l * 256;
        int cc = idx >> 6, n4 = idx & 63;
        xr[l] = *(const float4*)&x[(b * NC + cc) * NHW + n0 + n4 * 4];
    }

    for (int ch = 0; ch < 8; ch++) {
        __syncthreads();
        #pragma unroll
        for (int l = 0; l < 8; l++) {
            int idx = t + l * 256;
            int cc = idx >> 6, n4 = idx & 63;
            *(uint2*)(sm + OFF_X + cc * QW_PITCH + n4 * 8) =
                make_uint2(pack_bf16(xr[l].y, xr[l].x), pack_bf16(xr[l].w, xr[l].z));
        }
        __syncthreads();
        if (ch + 1 < 8) {
            int c0n = (ch + 1) * 32;
            #pragma unroll
            for (int l = 0; l < 8; l++) {
                int idx = t + l * 256;
                int cc = idx >> 6, n4 = idx & 63;
                xr[l] = *(const float4*)&x[(b * NC + c0n + cc) * NHW + n0 + n4 * 4];
            }
        }
        #pragma unroll
        for (int ks = 0; ks < 2; ks++) {
            const int cb = ks * 16;
            uint32_t a0[4], a1[4];
            uint32_t wadr = sb + OFF_W + (wOC * 32 + (lane & 15)) * QW_PITCH
                            + (ch * 32 + cb) * 2 + (lane >> 4) * 16;
            ldmx4(a0, wadr);
            ldmx4(a1, wadr + 16 * QW_PITCH);
            uint32_t bt[4][4];
            #pragma unroll
            for (int nb = 0; nb < 4; nb++) {
                uint32_t xadr = sb + OFF_X
                    + (cb + (lane & 7) + ((lane >> 3) & 1) * 8) * QW_PITCH
                    + (wN * 64 + nb * 16 + (lane >> 4) * 8) * 2;
                ldmx4t(bt[nb], xadr);
            }
            #pragma unroll
            for (int nb = 0; nb < 4; nb++) {
                mma_bf16(acc[0][nb * 2],     a0, bt[nb][0], bt[nb][1]);
                mma_bf16(acc[0][nb * 2 + 1], a0, bt[nb][2], bt[nb][3]);
                mma_bf16(acc[1][nb * 2],     a1, bt[nb][0], bt[nb][1]);
                mma_bf16(acc[1][nb * 2 + 1], a1, bt[nb][2], bt[nb][3]);
            }
        }
    }
    __syncthreads();

    const float* bs = (const float*)(sm + OFF_BIAS);
    float bm[2][2];
    bm[0][0] = bs[wOC * 32 + r];      bm[0][1] = bs[wOC * 32 + r + 8];
    bm[1][0] = bs[wOC * 32 + 16 + r]; bm[1][1] = bs[wOC * 32 + 16 + r + 8];
    __syncthreads();

    if (oc0 == 0) {
        const float scl = (wOC == 0) ? 1.4426950408889634f : 1.0f;
        #pragma unroll
        for (int m = 0; m < 2; m++) {
            int oc_r0 = wOC * 32 + m * 16 + r;
            #pragma unroll
            for (int j = 0; j < 8; j++) {
                int n_ = wN * 64 + j * 8 + tq * 2;
                *(__nv_bfloat16*)(sm + n_ * 144 + oc_r0 * 2) =
                    __float2bfloat16((acc[m][j][0] + bm[m][0]) * scl);
                *(__nv_bfloat16*)(sm + (n_ + 1) * 144 + oc_r0 * 2) =
                    __float2bfloat16((acc[m][j][1] + bm[m][0]) * scl);
                *(__nv_bfloat16*)(sm + n_ * 144 + (oc_r0 + 8) * 2) =
                    __float2bfloat16((acc[m][j][2] + bm[m][1]) * scl);
                *(__nv_bfloat16*)(sm + (n_ + 1) * 144 + (oc_r0 + 8) * 2) =
                    __float2bfloat16((acc[m][j][3] + bm[m][1]) * scl);
            }
        }
        __syncthreads();
        #pragma unroll
        for (int l = 0; l < 4; l++) {
            int idx = t + l * 256;
            int nn = idx >> 2, c4 = idx & 3;
            *(float4*)&g_Qb[b][n0 + nn][c4 * 8] =
                *(const float4*)(sm + nn * 144 + c4 * 16);
            *(float4*)&g_Kb[b][n0 + nn][c4 * 8] =
                *(const float4*)(sm + nn * 144 + 64 + c4 * 16);
        }
    } else {
        #pragma unroll
        for (int m = 0; m < 2; m++) {
            int row0 = wOC * 32 + m * 16 + r;
            #pragma unroll
            for (int j = 0; j < 8; j++) {
                int n_ = wN * 64 + j * 8 + tq * 2;
                *(uint32_t*)(sm + row0 * 528 + n_ * 2) =
                    pack_bf16(acc[m][j][1] + bm[m][0], acc[m][j][0] + bm[m][0]);
                *(uint32_t*)(sm + (row0 + 8) * 528 + n_ * 2) =
                    pack_bf16(acc[m][j][3] + bm[m][1], acc[m][j][2] + bm[m][1]);
            }
        }
        __syncthreads();
        #pragma unroll
        for (int l = 0; l < 8; l++) {
            int idx = t + l * 256;
            int row = idx >> 5, n16 = idx & 31;
            *(float4*)&g_Vb[b][oc0 - 64 + row][n0 + n16 * 8] =
                *(const float4*)(sm + row * 528 + n16 * 16);
        }
    }
}

// ============================================================================
// Kernel B: flash attention, 3-axis warp tiling + cross-iteration P-exchange.
// CTA 64q x 128E, 8 warps = 2 wM(32q) x 2 wE(64E) x 2 wK(32-key half).
// Per iter:
//   - warp computes QK+exp+pack its 32 rows x 16-key quarter (q_idx=wK*2+wE)
//     of tile i+1 and publishes A-frags to pbuf[(i+1)&1];
//   - PV(i): warp accumulates its 32-key HALF into its 32q x 64E O (64 regs),
//     A-frags for 2 k16 slots from pbuf, V frags 8 ldmx4 (8 eb of 8 E-rows).
// P-read redundancy 4x -> 2x vs R13. wK halves of O merged once in epilogue.
// ============================================================================
#define OFF_Q 0
#define OFF_K 5120             // 3 x 5120
#define OFF_V 20480            // 3 x 18432
#define OFF_PB 75776           // 2 x 8192 (4 m16 x 4 k16 x 32 lanes x 16B)
#define OFF_SUM 92160          // 4 x 64 f32
#define ATTN_SMEM_B 93184

__global__ __launch_bounds__(256, 2) void attn_kernel(
    const float* __restrict__ x,
    const float* __restrict__ gamma_p,
    float* __restrict__ out)
{
    extern __shared__ char smem[];
    const uint32_t sb = smem_u32(smem);
    const int t = threadIdx.x, wid = t >> 5, lane = t & 31;
    const int b = blockIdx.z;
    const int n0 = blockIdx.x * 64;
    const int e0 = blockIdx.y * 128;
    const int wE = wid & 1, wK = (wid >> 1) & 1, wM = wid >> 2;
    const int q_idx = wK * 2 + wE;           // 16-key quarter owned for QK/exp
    const int r = lane >> 2, tq = lane & 3;

    const int krow = t >> 2, kch = t & 3;

    // ---- prologue: G0={Q,K0}  G1={V0,K1}  G2={V1} ----
    cpa16(sb + OFF_Q + krow * 80 + kch * 16, &g_Qb[b][n0 + krow][kch * 8]);
    cpa16(sb + OFF_K + krow * 80 + kch * 16, &g_Kb[b][krow][kch * 8]);
    CP_COMMIT();
    #pragma unroll
    for (int l = 0; l < 4; l++) {
        int c = t + l * 256;
        int e = c >> 3, ch8 = c & 7;
        cpa16(sb + OFF_V + e * 144 + ch8 * 16, &g_Vb[b][e0 + e][ch8 * 8]);
    }
    cpa16(sb + OFF_K + 5120 + krow * 80 + kch * 16, &g_Kb[b][64 + krow][kch * 8]);
    CP_COMMIT();
    #pragma unroll
    for (int l = 0; l < 4; l++) {
        int c = t + l * 256;
        int e = c >> 3, ch8 = c & 7;
        cpa16(sb + OFF_V + 18432 + e * 144 + ch8 * 16, &g_Vb[b][e0 + e][64 + ch8 * 8]);
    }
    CP_COMMIT();

    CP_WAIT2();                  // G0 done: Q + K0 resident
    __syncthreads();

    // persistent Q fragments for 32 rows: qa[m16 half][d-kstep]
    uint32_t qa[2][2][4];
    #pragma unroll
    for (int m = 0; m < 2; m++) {
        uint32_t qaddr = sb + OFF_Q + (wM * 32 + m * 16 + (lane & 15)) * 80
                         + (lane >> 4) * 16;
        ldmx4(qa[m][0], qaddr);
        ldmx4(qa[m][1], qaddr + 32);
    }
    const uint32_t k_off = (lane & 7) * 80 + (lane >> 3) * 16;
    const uint32_t v_off = (wE * 64 + (lane & 7)) * 144 + (lane >> 3) * 16;
    const uint32_t px_lane = (uint32_t)lane * 16;

    float o[2][8][4];            // [m16 half][eb 8-E-row group][frag]
    #pragma unroll
    for (int m = 0; m < 2; m++)
        #pragma unroll
        for (int eb = 0; eb < 8; eb++)
            #pragma unroll
            for (int j = 0; j < 4; j++) o[m][eb][j] = 0.f;
    float sums_r[2][2] = {{0.f, 0.f}, {0.f, 0.f}};   // [m][row r / r+8]

    // ---- compute P(J) for own 32 rows x 16-key quarter, publish ----
    #define COMPUTE_P_HALF(J)                                                     \
    {                                                                             \
        const uint32_t kb_ = sb + OFF_K + ((J) % 3) * 5120;                       \
        const uint32_t pb_ = sb + OFF_PB + ((J) & 1) * 8192;                      \
        float c_[2][2][4];                                                        \
        _Pragma("unroll")                                                         \
        for (int g = 0; g < 2; g++) {                                             \
            uint32_t kf[4];                                                       \
            ldmx4(kf, kb_ + (q_idx * 16 + g * 8) * 80 + k_off);                   \
            _Pragma("unroll")                                                     \
            for (int m = 0; m < 2; m++) {                                         \
                c_[m][g][0] = c_[m][g][1] = c_[m][g][2] = c_[m][g][3] = 0.f;      \
                mma_bf16(c_[m][g], qa[m][0], kf[0], kf[1]);                       \
                mma_bf16(c_[m][g], qa[m][1], kf[2], kf[3]);                       \
            }                                                                     \
        }                                                                         \
        _Pragma("unroll")                                                         \
        for (int m = 0; m < 2; m++) {                                             \
            float p0 = fexp2(c_[m][0][0]), p1 = fexp2(c_[m][0][1]);               \
            float p2 = fexp2(c_[m][0][2]), p3 = fexp2(c_[m][0][3]);               \
            float q0 = fexp2(c_[m][1][0]), q1 = fexp2(c_[m][1][1]);               \
            float q2 = fexp2(c_[m][1][2]), q3 = fexp2(c_[m][1][3]);               \
            sums_r[m][0] += p0 + p1 + q0 + q1;                                    \
            sums_r[m][1] += p2 + p3 + q2 + q3;                                    \
            *(uint4*)((char*)smem + (pb_ - sb)                                    \
                      + (((wM * 2 + m) * 4 + q_idx) * 32) * 16 + px_lane) =       \
                make_uint4(pack_bf16(p1, p0), pack_bf16(p3, p2),                  \
                           pack_bf16(q1, q0), pack_bf16(q3, q2));                 \
        }                                                                         \
    }

    COMPUTE_P_HALF(0);

    for (int i = 0; i < 64; i++) {
        if (i < 63) { CP_WAIT1(); } else { CP_WAIT0(); }
        __syncthreads();               // V(i)+K(i+1) ready; P(i) exchange visible

        if (i + 2 < 64) {              // prefetch tile i+2: K group, then V group
            int m0 = (i + 2) * 64;
            cpa16(sb + OFF_K + ((i + 2) % 3) * 5120 + krow * 80 + kch * 16,
                  &g_Kb[b][m0 + krow][kch * 8]);
            CP_COMMIT();
            uint32_t vst = sb + OFF_V + ((i + 2) % 3) * 18432;
            #pragma unroll
            for (int l = 0; l < 4; l++) {
                int c = t + l * 256;
                int e = c >> 3, ch8 = c & 7;
                cpa16(vst + e * 144 + ch8 * 16, &g_Vb[b][e0 + e][m0 + ch8 * 8]);
            }
            CP_COMMIT();
        }

        if (i + 1 < 64) COMPUTE_P_HALF(i + 1);

        // ---- PV(i): own 32-key half (k16 slots 2wK, 2wK+1), 64 E-cols ----
        uint32_t pau[2][2][4];         // [m][k16 within half]
        #pragma unroll
        for (int m = 0; m < 2; m++)
            #pragma unroll
            for (int s = 0; s < 2; s++) {
                uint4 u = *(const uint4*)((char*)smem + OFF_PB + (i & 1) * 8192
                          + (((wM * 2 + m) * 4 + wK * 2 + s) * 32) * 16 + px_lane);
                pau[m][s][0] = u.x; pau[m][s][1] = u.y;
                pau[m][s][2] = u.z; pau[m][s][3] = u.w;
            }
        const uint32_t vb = sb + OFF_V + (i % 3) * 18432 + wK * 64;
        #pragma unroll
        for (int eb = 0; eb < 8; eb++) {
            uint32_t v[4];
            ldmx4(v, vb + v_off + eb * 1152);
            #pragma unroll
            for (int m = 0; m < 2; m++) {
                mma_bf16(o[m][eb], pau[m][0], v[0], v[1]);
                mma_bf16(o[m][eb], pau[m][1], v[2], v[3]);
            }
        }
    }

    // ---- merge rowsum quarters ----
    #pragma unroll
    for (int m = 0; m < 2; m++)
        #pragma unroll
        for (int h = 0; h < 2; h++) {
            sums_r[m][h] += __shfl_xor_sync(0xffffffffu, sums_r[m][h], 1);
            sums_r[m][h] += __shfl_xor_sync(0xffffffffu, sums_r[m][h], 2);
        }
    float* sums = (float*)(smem + OFF_SUM);   // [4 quarters][64 rows]
    __syncthreads();                           // all PV reads done
    if (tq == 0) {
        #pragma unroll
        for (int m = 0; m < 2; m++)
            #pragma unroll
            for (int h = 0; h < 2; h++)
                sums[q_idx * 64 + wM * 32 + m * 16 + h * 8 + r] = sums_r[m][h];
    }
    __syncthreads();
    const float g = gamma_p[0];
    float scl[2][2];
    #pragma unroll
    for (int m = 0; m < 2; m++)
        #pragma unroll
        for (int h = 0; h < 2; h++) {
            int row = wM * 32 + m * 16 + h * 8 + r;
            scl[m][h] = g / (sums[row] + sums[64 + row] + sums[128 + row]
                             + sums[192 + row]);
        }

    // ---- stage O with wK merge ----
    float* os = (float*)smem;                 // [64][133]
    if (wK == 0) {
        #pragma unroll
        for (int m = 0; m < 2; m++)
            #pragma unroll
            for (int eb = 0; eb < 8; eb++) {
                int e = wE * 64 + eb * 8 + 2 * tq;
                int row0 = wM * 32 + m * 16 + r;
                os[row0 * 133 + e]           = o[m][eb][0] * scl[m][0];
                os[row0 * 133 + e + 1]       = o[m][eb][1] * scl[m][0];
                os[(row0 + 8) * 133 + e]     = o[m][eb][2] * scl[m][1];
                os[(row0 + 8) * 133 + e + 1] = o[m][eb][3] * scl[m][1];
            }
    }
    __syncthreads();
    if (wK == 1) {
        #pragma unroll
        for (int m = 0; m < 2; m++)
            #pragma unroll
            for (int eb = 0; eb < 8; eb++) {
                int e = wE * 64 + eb * 8 + 2 * tq;
                int row0 = wM * 32 + m * 16 + r;
                os[row0 * 133 + e]           += o[m][eb][0] * scl[m][0];
                os[row0 * 133 + e + 1]       += o[m][eb][1] * scl[m][0];
                os[(row0 + 8) * 133 + e]     += o[m][eb][2] * scl[m][1];
                os[(row0 + 8) * 133 + e + 1] += o[m][eb][3] * scl[m][1];
            }
    }
    __syncthreads();
    #pragma unroll 8
    for (int l = 0; l < 32; l++) {
        int idx = t + l * 256;
        int n = idx & 63, e = idx >> 6;
        int gi = (b * NC + e0 + e) * NHW + n0 + n;
        out[gi] = os[n * 133 + e] + x[gi];
    }
}

// ============================================================================
extern "C" void kernel_launch(void* const* d_in, const int* in_sizes, int n_in,
                              void* d_out, int out_size) {
    (void)in_sizes; (void)n_in; (void)out_size;
    const float* x     = (const float*)d_in[0];
    const float* Wq    = (const float*)d_in[1];
    const float* bq    = (const float*)d_in[2];
    const float* Wk    = (const float*)d_in[3];
    const float* bk    = (const float*)d_in[4];
    const float* Wv    = (const float*)d_in[5];
    const float* bv    = (const float*)d_in[6];
    const float* gamma = (const float*)d_in[7];
    float* out = (float*)d_out;

    cudaFuncSetAttribute(qkv_kernel,
                         cudaFuncAttributeMaxDynamicSharedMemorySize, QKV_SMEM2);
    cudaFuncSetAttribute(attn_kernel,
                         cudaFuncAttributeMaxDynamicSharedMemorySize, ATTN_SMEM_B);

    dim3 gA(16, 5, NB);
    qkv_kernel<<<gA, 256, QKV_SMEM2>>>(x, Wq, bq, Wk, bk, Wv, bv);

    dim3 gB(64, 2, NB);
    attn_kernel<<<gB, 256, ATTN_SMEM_B>>>(x, gamma, out);
}

// round 16
// speedup vs baseline: 1.1041x; 1.0762x over previous
#include <cuda_runtime.h>
#include <cuda_bf16.h>
#include <cstdint>

#define NB 8
#define NC 256
#define NHW 4096
#define ND 32

typedef unsigned long long ull;

// Static device scratch
__device__ __nv_bfloat16 g_Qb[NB][NHW][ND];    // q * log2(e), [b][n][d] bf16
__device__ __nv_bfloat16 g_Kb[NB][NHW][ND];    // [b][n][d] bf16
__device__ __nv_bfloat16 g_Vb[NB][NC][NHW];    // [b][e][n] bf16

// ---------------------------------------------------------------------------
// helpers
// ---------------------------------------------------------------------------
__device__ __forceinline__ uint32_t smem_u32(const void* p) {
    uint32_t a;
    asm("{ .reg .u64 t; cvta.to.shared.u64 t, %1; cvt.u32.u64 %0, t; }"
        : "=r"(a) : "l"(p));
    return a;
}
__device__ __forceinline__ float fexp2(float v) {
    float r; asm("ex2.approx.ftz.f32 %0, %1;" : "=f"(r) : "f"(v)); return r;
}
// d = {hi, lo} packed bf16x2
__device__ __forceinline__ uint32_t pack_bf16(float hi, float lo) {
    uint32_t r; asm("cvt.rn.bf16x2.f32 %0, %1, %2;" : "=r"(r) : "f"(hi), "f"(lo));
    return r;
}
__device__ __forceinline__ void mma_bf16(float c[4], const uint32_t a[4],
                                         uint32_t b0, uint32_t b1) {
    asm volatile(
        "mma.sync.aligned.m16n8k16.row.col.f32.bf16.bf16.f32 "
        "{%0,%1,%2,%3}, {%4,%5,%6,%7}, {%8,%9}, {%0,%1,%2,%3};"
        : "+f"(c[0]), "+f"(c[1]), "+f"(c[2]), "+f"(c[3])
        : "r"(a[0]), "r"(a[1]), "r"(a[2]), "r"(a[3]), "r"(b0), "r"(b1));
}
__device__ __forceinline__ void ldmx4(uint32_t r[4], uint32_t a) {
    asm volatile("ldmatrix.sync.aligned.m8n8.x4.shared.b16 {%0,%1,%2,%3}, [%4];"
        : "=r"(r[0]), "=r"(r[1]), "=r"(r[2]), "=r"(r[3]) : "r"(a));
}
__device__ __forceinline__ void ldmx4t(uint32_t r[4], uint32_t a) {
    asm volatile("ldmatrix.sync.aligned.m8n8.x4.trans.shared.b16 {%0,%1,%2,%3}, [%4];"
        : "=r"(r[0]), "=r"(r[1]), "=r"(r[2]), "=r"(r[3]) : "r"(a));
}
__device__ __forceinline__ void cpa16(uint32_t s, const void* g) {
    asm volatile("cp.async.cg.shared.global [%0], [%1], 16;"
                 :: "r"(s), "l"(__cvta_generic_to_global(g)) : "memory");
}
#define CP_COMMIT() asm volatile("cp.async.commit_group;" ::: "memory")
#define CP_WAIT2()  asm volatile("cp.async.wait_group 2;" ::: "memory")
#define CP_WAIT1()  asm volatile("cp.async.wait_group 1;" ::: "memory")
#define CP_WAIT0()  asm volatile("cp.async.wait_group 0;" ::: "memory")

// ============================================================================
// Kernel A: fused QKV projection, bf16 tensor cores (unchanged, ~15us).
// ============================================================================
#define QW_PITCH 528
#define OFF_W 0
#define OFF_BIAS 33792
#define OFF_X 34048
#define QKV_SMEM2 50944

__global__ __launch_bounds__(256) void qkv_kernel(
    const float* __restrict__ x,
    const float* __restrict__ Wq, const float* __restrict__ bq,
    const float* __restrict__ Wk, const float* __restrict__ bk,
    const float* __restrict__ Wv, const float* __restrict__ bv)
{
    extern __shared__ char sm[];
    const uint32_t sb = smem_u32(sm);
    const int b = blockIdx.z;
    const int oc0 = blockIdx.y * 64;
    const int n0 = blockIdx.x * 256;
    const int t = threadIdx.x, wid = t >> 5, lane = t & 31;
    const int wOC = wid & 1, wN = wid >> 1;
    const int r = lane >> 2, tq = lane & 3;

    #pragma unroll
    for (int l = 0; l < 16; l++) {
        int idx = t + l * 256;
        int row = idx >> 6, c4 = idx & 63;
        const float* src;
        if (oc0 == 0) src = (row < 32) ? &Wq[row * 256 + c4 * 4]
                                       : &Wk[(row - 32) * 256 + c4 * 4];
        else          src = &Wv[(oc0 - 64 + row) * 256 + c4 * 4];
        float4 w = *(const float4*)src;
        *(uint2*)(sm + OFF_W + row * QW_PITCH + c4 * 8) =
            make_uint2(pack_bf16(w.y, w.x), pack_bf16(w.w, w.z));
    }
    if (t < 64) {
        float bias;
        if (oc0 == 0) bias = (t < 32) ? bq[t] : bk[t - 32];
        else          bias = bv[oc0 - 64 + t];
        ((float*)(sm + OFF_BIAS))[t] = bias;
    }

    float acc[2][8][4];
    #pragma unroll
    for (int m = 0; m < 2; m++)
        #pragma unroll
        for (int j = 0; j < 8; j++)
            #pragma unroll
            for (int q = 0; q < 4; q++) acc[m][j][q] = 0.f;

    float4 xr[8];
    #pragma unroll
    for (int l = 0; l < 8; l++) {
        int idx = t + l * 256;
        int cc = idx >> 6, n4 = idx & 63;
        xr[l] = *(const float4*)&x[(b * NC + cc) * NHW + n0 + n4 * 4];
    }

    for (int ch = 0; ch < 8; ch++) {
        __syncthreads();
        #pragma unroll
        for (int l = 0; l < 8; l++) {
            int idx = t + l * 256;
            int cc = idx >> 6, n4 = idx & 63;
            *(uint2*)(sm + OFF_X + cc * QW_PITCH + n4 * 8) =
                make_uint2(pack_bf16(xr[l].y, xr[l].x), pack_bf16(xr[l].w, xr[l].z));
        }
        __syncthreads();
        if (ch + 1 < 8) {
            int c0n = (ch + 1) * 32;
            #pragma unroll
            for (int l = 0; l < 8; l++) {
                int idx = t + l * 256;
                int cc = idx >> 6, n4 = idx & 63;
                xr[l] = *(const float4*)&x[(b * NC + c0n + cc) * NHW + n0 + n4 * 4];
            }
        }
        #pragma unroll
        for (int ks = 0; ks < 2; ks++) {
            const int cb = ks * 16;
            uint32_t a0[4], a1[4];
            uint32_t wadr = sb + OFF_W + (wOC * 32 + (lane & 15)) * QW_PITCH
                            + (ch * 32 + cb) * 2 + (lane >> 4) * 16;
            ldmx4(a0, wadr);
            ldmx4(a1, wadr + 16 * QW_PITCH);
            uint32_t bt[4][4];
            #pragma unroll
            for (int nb = 0; nb < 4; nb++) {
                uint32_t xadr = sb + OFF_X
                    + (cb + (lane & 7) + ((lane >> 3) & 1) * 8) * QW_PITCH
                    + (wN * 64 + nb * 16 + (lane >> 4) * 8) * 2;
                ldmx4t(bt[nb], xadr);
            }
            #pragma unroll
            for (int nb = 0; nb < 4; nb++) {
                mma_bf16(acc[0][nb * 2],     a0, bt[nb][0], bt[nb][1]);
                mma_bf16(acc[0][nb * 2 + 1], a0, bt[nb][2], bt[nb][3]);
                mma_bf16(acc[1][nb * 2],     a1, bt[nb][0], bt[nb][1]);
                mma_bf16(acc[1][nb * 2 + 1], a1, bt[nb][2], bt[nb][3]);
            }
        }
    }
    __syncthreads();

    const float* bs = (const float*)(sm + OFF_BIAS);
    float bm[2][2];
    bm[0][0] = bs[wOC * 32 + r];      bm[0][1] = bs[wOC * 32 + r + 8];
    bm[1][0] = bs[wOC * 32 + 16 + r]; bm[1][1] = bs[wOC * 32 + 16 + r + 8];
    __syncthreads();

    if (oc0 == 0) {
        const float scl = (wOC == 0) ? 1.4426950408889634f : 1.0f;
        #pragma unroll
        for (int m = 0; m < 2; m++) {
            int oc_r0 = wOC * 32 + m * 16 + r;
            #pragma unroll
            for (int j = 0; j < 8; j++) {
                int n_ = wN * 64 + j * 8 + tq * 2;
                *(__nv_bfloat16*)(sm + n_ * 144 + oc_r0 * 2) =
                    __float2bfloat16((acc[m][j][0] + bm[m][0]) * scl);
                *(__nv_bfloat16*)(sm + (n_ + 1) * 144 + oc_r0 * 2) =
                    __float2bfloat16((acc[m][j][1] + bm[m][0]) * scl);
                *(__nv_bfloat16*)(sm + n_ * 144 + (oc_r0 + 8) * 2) =
                    __float2bfloat16((acc[m][j][2] + bm[m][1]) * scl);
                *(__nv_bfloat16*)(sm + (n_ + 1) * 144 + (oc_r0 + 8) * 2) =
                    __float2bfloat16((acc[m][j][3] + bm[m][1]) * scl);
            }
        }
        __syncthreads();
        #pragma unroll
        for (int l = 0; l < 4; l++) {
            int idx = t + l * 256;
            int nn = idx >> 2, c4 = idx & 3;
            *(float4*)&g_Qb[b][n0 + nn][c4 * 8] =
                *(const float4*)(sm + nn * 144 + c4 * 16);
            *(float4*)&g_Kb[b][n0 + nn][c4 * 8] =
                *(const float4*)(sm + nn * 144 + 64 + c4 * 16);
        }
    } else {
        #pragma unroll
        for (int m = 0; m < 2; m++) {
            int row0 = wOC * 32 + m * 16 + r;
            #pragma unroll
            for (int j = 0; j < 8; j++) {
                int n_ = wN * 64 + j * 8 + tq * 2;
                *(uint32_t*)(sm + row0 * 528 + n_ * 2) =
                    pack_bf16(acc[m][j][1] + bm[m][0], acc[m][j][0] + bm[m][0]);
                *(uint32_t*)(sm + (row0 + 8) * 528 + n_ * 2) =
                    pack_bf16(acc[m][j][3] + bm[m][1], acc[m][j][2] + bm[m][1]);
            }
        }
        __syncthreads();
        #pragma unroll
        for (int l = 0; l < 8; l++) {
            int idx = t + l * 256;
            int row = idx >> 5, n16 = idx & 31;
            *(float4*)&g_Vb[b][oc0 - 64 + row][n0 + n16 * 8] =
                *(const float4*)(sm + row * 528 + n16 * 16);
        }
    }
}

// ============================================================================
// Kernel B: flash attention = R13 champion (2x4 warp retile, key-split
// cross-iteration P-exchange) with ONE change: the iteration body interleaves
// PV(i) around COMPUTE_P(i+1)'s exp/pack so the MUFU+STS window is covered by
// independent PV MMAs:
//   barrier -> prefetch -> QK(i+1) MMAs -> PV(i) kp=0 (16 MMAs)
//           -> exp/pack/STS(i+1) -> PV(i) kp=1 (16 MMAs)
// Arithmetic bit-identical to R13.
// ============================================================================
#define OFF_Q 0
#define OFF_K 5120             // 3 x 5120
#define OFF_V 20480            // 3 x 18432
#define OFF_PB 75776           // 2 x 8192 (4 m16 x 4 kstep x 32 lanes x 16B)
#define OFF_SUM 92160          // 4 x 64 f32
#define ATTN_SMEM_B 93184

__global__ __launch_bounds__(256, 2) void attn_kernel(
    const float* __restrict__ x,
    const float* __restrict__ gamma_p,
    float* __restrict__ out)
{
    extern __shared__ char smem[];
    const uint32_t sb = smem_u32(smem);
    const int t = threadIdx.x, wid = t >> 5, lane = t & 31;
    const int b = blockIdx.z;
    const int n0 = blockIdx.x * 64;
    const int e0 = blockIdx.y * 128;
    const int wM = wid & 1, wE = wid >> 1;   // 2 x 4
    const int r = lane >> 2, tq = lane & 3;

    const int krow = t >> 2, kch = t & 3;

    // ---- prologue: G0={Q,K0}  G1={V0,K1}  G2={V1} ----
    cpa16(sb + OFF_Q + krow * 80 + kch * 16, &g_Qb[b][n0 + krow][kch * 8]);
    cpa16(sb + OFF_K + krow * 80 + kch * 16, &g_Kb[b][krow][kch * 8]);
    CP_COMMIT();
    #pragma unroll
    for (int l = 0; l < 4; l++) {
        int c = t + l * 256;
        int e = c >> 3, ch8 = c & 7;
        cpa16(sb + OFF_V + e * 144 + ch8 * 16, &g_Vb[b][e0 + e][ch8 * 8]);
    }
    cpa16(sb + OFF_K + 5120 + krow * 80 + kch * 16, &g_Kb[b][64 + krow][kch * 8]);
    CP_COMMIT();
    #pragma unroll
    for (int l = 0; l < 4; l++) {
        int c = t + l * 256;
        int e = c >> 3, ch8 = c & 7;
        cpa16(sb + OFF_V + 18432 + e * 144 + ch8 * 16, &g_Vb[b][e0 + e][64 + ch8 * 8]);
    }
    CP_COMMIT();

    CP_WAIT2();                  // G0 done: Q + K0 resident
    __syncthreads();

    // persistent Q fragments for 32 rows: qa[m16 half][kstep]
    uint32_t qa[2][2][4];
    #pragma unroll
    for (int m = 0; m < 2; m++) {
        uint32_t qaddr = sb + OFF_Q + (wM * 32 + m * 16 + (lane & 15)) * 80
                         + (lane >> 4) * 16;
        ldmx4(qa[m][0], qaddr);
        ldmx4(qa[m][1], qaddr + 32);
    }
    const uint32_t k_off = (lane & 7) * 80 + (lane >> 3) * 16;
    const uint32_t v_off = (wE * 32 + (lane & 7)) * 144 + (lane >> 3) * 16;
    const uint32_t px_lane = (uint32_t)lane * 16;

    float o[2][4][4];            // [m16 half][eb 8-col group][frag]
    #pragma unroll
    for (int m = 0; m < 2; m++)
        #pragma unroll
        for (int eb = 0; eb < 4; eb++)
            #pragma unroll
            for (int j = 0; j < 4; j++) o[m][eb][j] = 0.f;
    float sums_r[2][2] = {{0.f, 0.f}, {0.f, 0.f}};   // [m][row r / r+8]

    // ---- P(0): full QK+exp+pack+publish for own quarter ----
    {
        const uint32_t kb_ = sb + OFF_K;          // tile 0 in slot 0
        const uint32_t pb_ = sb + OFF_PB;         // buf 0
        float c_[2][2][4];
        #pragma unroll
        for (int g = 0; g < 2; g++) {
            uint32_t kf[4];
            ldmx4(kf, kb_ + (wE * 16 + g * 8) * 80 + k_off);
            #pragma unroll
            for (int m = 0; m < 2; m++) {
                c_[m][g][0] = c_[m][g][1] = c_[m][g][2] = c_[m][g][3] = 0.f;
                mma_bf16(c_[m][g], qa[m][0], kf[0], kf[1]);
                mma_bf16(c_[m][g], qa[m][1], kf[2], kf[3]);
            }
        }
        #pragma unroll
        for (int m = 0; m < 2; m++) {
            float p0 = fexp2(c_[m][0][0]), p1 = fexp2(c_[m][0][1]);
            float p2 = fexp2(c_[m][0][2]), p3 = fexp2(c_[m][0][3]);
            float q0 = fexp2(c_[m][1][0]), q1 = fexp2(c_[m][1][1]);
            float q2 = fexp2(c_[m][1][2]), q3 = fexp2(c_[m][1][3]);
            sums_r[m][0] += p0 + p1 + q0 + q1;
            sums_r[m][1] += p2 + p3 + q2 + q3;
            *(uint4*)((char*)smem + (pb_ - sb)
                      + (((wM * 2 + m) * 4 + wE) * 32) * 16 + px_lane) =
                make_uint4(pack_bf16(p1, p0), pack_bf16(p3, p2),
                           pack_bf16(q1, q0), pack_bf16(q3, q2));
        }
    }

    for (int i = 0; i < 64; i++) {
        if (i < 63) { CP_WAIT1(); } else { CP_WAIT0(); }
        __syncthreads();               // V(i)+K(i+1) ready; P(i) exchange visible

        if (i + 2 < 64) {              // prefetch tile i+2: K group, then V group
            int m0 = (i + 2) * 64;
            cpa16(sb + OFF_K + ((i + 2) % 3) * 5120 + krow * 80 + kch * 16,
                  &g_Kb[b][m0 + krow][kch * 8]);
            CP_COMMIT();
            uint32_t vst = sb + OFF_V + ((i + 2) % 3) * 18432;
            #pragma unroll
            for (int l = 0; l < 4; l++) {
                int c = t + l * 256;
                int e = c >> 3, ch8 = c & 7;
                cpa16(vst + e * 144 + ch8 * 16, &g_Vb[b][e0 + e][m0 + ch8 * 8]);
            }
            CP_COMMIT();
        }

        const uint32_t vb = sb + OFF_V + (i % 3) * 18432;
        const bool has_next = (i + 1 < 64);

        // ---- (A) QK MMAs for tile i+1 (own 16-key quarter) ----
        float c_[2][2][4];
        if (has_next) {
            const uint32_t kb_ = sb + OFF_K + ((i + 1) % 3) * 5120;
            #pragma unroll
            for (int g = 0; g < 2; g++) {
                uint32_t kf[4];
                ldmx4(kf, kb_ + (wE * 16 + g * 8) * 80 + k_off);
                #pragma unroll
                for (int m = 0; m < 2; m++) {
                    c_[m][g][0] = c_[m][g][1] = c_[m][g][2] = c_[m][g][3] = 0.f;
                    mma_bf16(c_[m][g], qa[m][0], kf[0], kf[1]);
                    mma_bf16(c_[m][g], qa[m][1], kf[2], kf[3]);
                }
            }
        }

        // ---- (B) PV(i) first half: kp = 0 ----
        {
            uint32_t pau[2][2][4];
            #pragma unroll
            for (int m = 0; m < 2; m++)
                #pragma unroll
                for (int s = 0; s < 2; s++) {
                    uint4 u = *(const uint4*)((char*)smem + OFF_PB + (i & 1) * 8192
                              + (((wM * 2 + m) * 4 + s) * 32) * 16 + px_lane);
                    pau[m][s][0] = u.x; pau[m][s][1] = u.y;
                    pau[m][s][2] = u.z; pau[m][s][3] = u.w;
                }
            #pragma unroll
            for (int eb = 0; eb < 4; eb++) {
                uint32_t v[4];
                ldmx4(v, vb + v_off + eb * 1152);
                #pragma unroll
                for (int m = 0; m < 2; m++) {
                    mma_bf16(o[m][eb], pau[m][0], v[0], v[1]);
                    mma_bf16(o[m][eb], pau[m][1], v[2], v[3]);
                }
            }
        }

        // ---- (C) exp/pack/publish P(i+1) — hidden under (B)/(D) MMAs ----
        if (has_next) {
            const uint32_t pb_ = sb + OFF_PB + ((i + 1) & 1) * 8192;
            #pragma unroll
            for (int m = 0; m < 2; m++) {
                float p0 = fexp2(c_[m][0][0]), p1 = fexp2(c_[m][0][1]);
                float p2 = fexp2(c_[m][0][2]), p3 = fexp2(c_[m][0][3]);
                float q0 = fexp2(c_[m][1][0]), q1 = fexp2(c_[m][1][1]);
                float q2 = fexp2(c_[m][1][2]), q3 = fexp2(c_[m][1][3]);
                sums_r[m][0] += p0 + p1 + q0 + q1;
                sums_r[m][1] += p2 + p3 + q2 + q3;
                *(uint4*)((char*)smem + (pb_ - sb)
                          + (((wM * 2 + m) * 4 + wE) * 32) * 16 + px_lane) =
                    make_uint4(pack_bf16(p1, p0), pack_bf16(p3, p2),
                               pack_bf16(q1, q0), pack_bf16(q3, q2));
            }
        }

        // ---- (D) PV(i) second half: kp = 1 ----
        {
            uint32_t pau[2][2][4];
            #pragma unroll
            for (int m = 0; m < 2; m++)
                #pragma unroll
                for (int s = 0; s < 2; s++) {
                    uint4 u = *(const uint4*)((char*)smem + OFF_PB + (i & 1) * 8192
                              + (((wM * 2 + m) * 4 + 2 + s) * 32) * 16 + px_lane);
                    pau[m][s][0] = u.x; pau[m][s][1] = u.y;
                    pau[m][s][2] = u.z; pau[m][s][3] = u.w;
                }
            #pragma unroll
            for (int eb = 0; eb < 4; eb++) {
                uint32_t v[4];
                ldmx4(v, vb + v_off + eb * 1152 + 64);
                #pragma unroll
                for (int m = 0; m < 2; m++) {
                    mma_bf16(o[m][eb], pau[m][0], v[0], v[1]);
                    mma_bf16(o[m][eb], pau[m][1], v[2], v[3]);
                }
            }
        }
    }

    // ---- merge rowsum quarters across the 4 wE warps ----
    #pragma unroll
    for (int m = 0; m < 2; m++)
        #pragma unroll
        for (int h = 0; h < 2; h++) {
            sums_r[m][h] += __shfl_xor_sync(0xffffffffu, sums_r[m][h], 1);
            sums_r[m][h] += __shfl_xor_sync(0xffffffffu, sums_r[m][h], 2);
        }
    float* sums = (float*)(smem + OFF_SUM);   // [4 wE][64 rows]
    __syncthreads();
    if (tq == 0) {
        #pragma unroll
        for (int m = 0; m < 2; m++)
            #pragma unroll
            for (int h = 0; h < 2; h++)
                sums[wE * 64 + wM * 32 + m * 16 + h * 8 + r] = sums_r[m][h];
    }
    __syncthreads();
    const float g = gamma_p[0];
    float scl[2][2];
    #pragma unroll
    for (int m = 0; m < 2; m++)
        #pragma unroll
        for (int h = 0; h < 2; h++) {
            int row = wM * 32 + m * 16 + h * 8 + r;
            scl[m][h] = g / (sums[row] + sums[64 + row] + sums[128 + row]
                             + sums[192 + row]);
        }

    __syncthreads();
    float* os = (float*)smem;                 // [64][133]
    #pragma unroll
    for (int m = 0; m < 2; m++)
        #pragma unroll
        for (int eb = 0; eb < 4; eb++) {
            int e = wE * 32 + eb * 8 + 2 * tq;
            int row0 = wM * 32 + m * 16 + r;
            os[row0 * 133 + e]           = o[m][eb][0] * scl[m][0];
            os[row0 * 133 + e + 1]       = o[m][eb][1] * scl[m][0];
            os[(row0 + 8) * 133 + e]     = o[m][eb][2] * scl[m][1];
            os[(row0 + 8) * 133 + e + 1] = o[m][eb][3] * scl[m][1];
        }
    __syncthreads();
    #pragma unroll 8
    for (int l = 0; l < 32; l++) {
        int idx = t + l * 256;
        int n = idx & 63, e = idx >> 6;
        int gi = (b * NC + e0 + e) * NHW + n0 + n;
        out[gi] = os[n * 133 + e] + x[gi];
    }
}

// ============================================================================
extern "C" void kernel_launch(void* const* d_in, const int* in_sizes, int n_in,
                              void* d_out, int out_size) {
    (void)in_sizes; (void)n_in; (void)out_size;
    const float* x     = (const float*)d_in[0];
    const float* Wq    = (const float*)d_in[1];
    const float* bq    = (const float*)d_in[2];
    const float* Wk    = (const float*)d_in[3];
    const float* bk    = (const float*)d_in[4];
    const float* Wv    = (const float*)d_in[5];
    const float* bv    = (const float*)d_in[6];
    const float* gamma = (const float*)d_in[7];
    float* out = (float*)d_out;

    cudaFuncSetAttribute(qkv_kernel,
                         cudaFuncAttributeMaxDynamicSharedMemorySize, QKV_SMEM2);
    cudaFuncSetAttribute(attn_kernel,
                         cudaFuncAttributeMaxDynamicSharedMemorySize, ATTN_SMEM_B);

    dim3 gA(16, 5, NB);
    qkv_kernel<<<gA, 256, QKV_SMEM2>>>(x, Wq, bq, Wk, bk, Wv, bv);

    dim3 gB(64, 2, NB);
    attn_kernel<<<gB, 256, ATTN_SMEM_B>>>(x, gamma, out);
}